// round 15
// baseline (speedup 1.0000x reference)
#include <cuda_runtime.h>
#include <cuda_bf16.h>
#include <cuda_fp16.h>
#include <stdint.h>
#include <math.h>

// Problem constants
#define SEQ   2048
#define HID   4096
#define NH    32
#define NKV   8
#define HD    128
#define KVHID 1024      // NKV*HD
#define KVW   2048      // merged k|v row width

// Scratch (device globals; allocation-free rule)
__device__ __half g_qth[SEQ * HID];      // roped, scaled Q (fp16)
__device__ __half g_kh[SEQ * KVHID];     // roped K (fp16)
__device__ __half g_vth[NKV * HD * SEQ]; // V^T (fp16): [kvh][d][s]
__device__ __half g_attnh[SEQ * HID];    // attention output (fp16)

// fp16 copies of inputs for tensor-core GEMMs
__device__ __half g_hsh[SEQ * HID];
__device__ __half g_qwh[HID * HID];
__device__ __half g_kvwh[KVW * HID];     // rows 0-1023 = k_proj, 1024-2047 = v_proj
__device__ __half g_owh[HID * HID];

// ---------------------------------------------------------------------------
// Helpers
// ---------------------------------------------------------------------------
__device__ __forceinline__ void mma_f16(float* c, const uint32_t* a,
                                        const uint32_t* b) {
    asm volatile(
        "mma.sync.aligned.m16n8k16.row.col.f32.f16.f16.f32 "
        "{%0,%1,%2,%3}, {%4,%5,%6,%7}, {%8,%9}, {%0,%1,%2,%3};"
        : "+f"(c[0]), "+f"(c[1]), "+f"(c[2]), "+f"(c[3])
        : "r"(a[0]), "r"(a[1]), "r"(a[2]), "r"(a[3]), "r"(b[0]), "r"(b[1]));
}

// ldmatrix x4: loads four 8x8 b16 matrices. Lane l supplies the address of
// row (l&15) / k-half (l>>4) of a 16x16 tile; result regs map exactly to the
// mma A-fragment order (r0=row g k-lo, r1=row g+8 k-lo, r2=k-hi, r3=both).
__device__ __forceinline__ void ldsm_x4(uint32_t* r, uint32_t addr) {
    asm volatile(
        "ldmatrix.sync.aligned.m8n8.x4.shared.b16 {%0,%1,%2,%3}, [%4];"
        : "=r"(r[0]), "=r"(r[1]), "=r"(r[2]), "=r"(r[3])
        : "r"(addr));
}

__device__ __forceinline__ void cp16(uint32_t saddr, const void* gaddr) {
    asm volatile("cp.async.cg.shared.global [%0], [%1], 16;"
                 :: "r"(saddr), "l"(gaddr));
}
__device__ __forceinline__ void cp_commit() {
    asm volatile("cp.async.commit_group;");
}
template <int N>
__device__ __forceinline__ void cp_wait() {
    asm volatile("cp.async.wait_group %0;" :: "n"(N));
}

// ---------------------------------------------------------------------------
// Fused fp32->fp16 conversion of all 5 inputs, one launch, MLP=4.
// ---------------------------------------------------------------------------
#define CVT_S0 (SEQ * HID / 4)                         // hs    : 2M
#define CVT_S1 (CVT_S0 + HID * HID / 4)                // qw    : +4M
#define CVT_S2 (CVT_S1 + KVHID * HID / 4)              // kw    : +1M
#define CVT_S3 (CVT_S2 + KVHID * HID / 4)              // vw    : +1M
#define CVT_S4 (CVT_S3 + HID * HID / 4)                // ow    : +4M
#define CVT_BLOCKS (CVT_S4 / 1024)

__global__ __launch_bounds__(256) void cvt_all(const float* __restrict__ hs,
                                               const float* __restrict__ qw,
                                               const float* __restrict__ kw,
                                               const float* __restrict__ vw,
                                               const float* __restrict__ ow,
                                               __half* __restrict__ hsh,
                                               __half* __restrict__ qwh,
                                               __half* __restrict__ kvwh,
                                               __half* __restrict__ owh) {
    const long long base = (long long)blockIdx.x * 1024;
    const float* src;
    __half2* dst;
    long long off;
    if (base < CVT_S0)      { src = hs; dst = (__half2*)hsh;  off = base; }
    else if (base < CVT_S1) { src = qw; dst = (__half2*)qwh;  off = base - CVT_S0; }
    else if (base < CVT_S2) { src = kw; dst = (__half2*)kvwh; off = base - CVT_S1; }
    else if (base < CVT_S3) { src = vw; dst = (__half2*)(kvwh + (size_t)KVHID * HID);
                              off = base - CVT_S2; }
    else                    { src = ow; dst = (__half2*)owh;  off = base - CVT_S3; }

    float4 x[4];
#pragma unroll
    for (int j = 0; j < 4; j++)
        x[j] = ((const float4*)src)[off + threadIdx.x + j * 256];
#pragma unroll
    for (int j = 0; j < 4; j++) {
        long long f = off + threadIdx.x + j * 256;
        dst[2 * f]     = __floats2half2_rn(x[j].x, x[j].y);
        dst[2 * f + 1] = __floats2half2_rn(x[j].z, x[j].w);
    }
}

// ---------------------------------------------------------------------------
// fp16 tensor-core GEMM core with ldmatrix fragment loads, templated epilogue.
// ---------------------------------------------------------------------------
#define HSTRIDE 72
#define HSTAGES 3
#define HGEMM_SMEM (HSTAGES * 2 * 128 * HSTRIDE * 2)   // 110592 B
#define SST 132   // fp32 smem staging stride (EVEN -> float2-aligned; 4 mod 32)

template <typename EPI>
__device__ __forceinline__ void hgemm_tile_core(const __half* __restrict__ A,
                                                const __half* __restrict__ W,
                                                int K, int mb, int nb,
                                                char* gsm, EPI&& epi) {
    __half* As = (__half*)gsm;                       // [3][128][72]
    __half* Bs = As + HSTAGES * 128 * HSTRIDE;

    const int tid  = threadIdx.x;
    const int lane = tid & 31;
    const int wid  = tid >> 5;
    const int g    = lane >> 2;
    const int tg   = lane & 3;
    const int wm   = (wid >> 1) * 32;
    const int wn   = (wid & 1) * 64;
    const int lrow = lane & 15;          // ldmatrix row within 16x16 tile
    const int lcol = (lane >> 4) * 8;    // ldmatrix k-half (halves)

    const __half* Ap = A + (size_t)mb * K;
    const __half* Wp = W + (size_t)nb * K;

    const uint32_t sA = (uint32_t)__cvta_generic_to_shared(As);
    const uint32_t sB = (uint32_t)__cvta_generic_to_shared(Bs);

    auto issue_stage = [&](int stage, int k0) {
        const uint32_t so = (uint32_t)(stage * 128 * HSTRIDE * 2);
#pragma unroll
        for (int j = 0; j < 4; j++) {
            int idx = tid + 256 * j;
            int row = idx >> 3, ch = idx & 7;
            uint32_t sofs = so + (uint32_t)(row * HSTRIDE * 2 + ch * 16);
            cp16(sA + sofs, Ap + (size_t)row * K + k0 + ch * 8);
            cp16(sB + sofs, Wp + (size_t)row * K + k0 + ch * 8);
        }
    };

    float acc[2][8][4];
#pragma unroll
    for (int i = 0; i < 2; i++)
#pragma unroll
        for (int j = 0; j < 8; j++)
#pragma unroll
            for (int t = 0; t < 4; t++) acc[i][j][t] = 0.f;

    const int NIT = K / 64;
    issue_stage(0, 0);  cp_commit();
    issue_stage(1, 64); cp_commit();
    cp_wait<1>();
    __syncthreads();

    for (int it = 0; it < NIT; it++) {
        const int s = it % HSTAGES;
        const uint32_t aoff = sA + (uint32_t)(s * 128 * HSTRIDE * 2);
        const uint32_t boff = sB + (uint32_t)(s * 128 * HSTRIDE * 2);

#pragma unroll
        for (int kk = 0; kk < 4; kk++) {
            uint32_t af[2][4], bf[8][2];
#pragma unroll
            for (int i = 0; i < 2; i++)
                ldsm_x4(af[i], aoff + (uint32_t)(((wm + i * 16 + lrow) * HSTRIDE
                                                  + kk * 16 + lcol) * 2));
#pragma unroll
            for (int jj = 0; jj < 4; jj++) {
                uint32_t t[4];
                ldsm_x4(t, boff + (uint32_t)(((wn + jj * 16 + lrow) * HSTRIDE
                                              + kk * 16 + lcol) * 2));
                bf[2 * jj][0] = t[0]; bf[2 * jj + 1][0] = t[1];
                bf[2 * jj][1] = t[2]; bf[2 * jj + 1][1] = t[3];
            }
#pragma unroll
            for (int i = 0; i < 2; i++)
#pragma unroll
                for (int j = 0; j < 8; j++)
                    mma_f16(acc[i][j], af[i], bf[j]);
        }

        if (it + 2 < NIT) issue_stage((it + 2) % HSTAGES, (it + 2) * 64);
        cp_commit();
        cp_wait<1>();
        __syncthreads();
    }

    epi(acc, wm, wn, g, tg);
}

// o_proj: plain fp32 store epilogue
__global__ __launch_bounds__(256, 2) void gemm_f16(const __half* __restrict__ A,
                                                   const __half* __restrict__ W,
                                                   float* __restrict__ C,
                                                   int N, int K) {
    extern __shared__ char gsm[];
    const int mb = blockIdx.y * 128, nb = blockIdx.x * 128;
    hgemm_tile_core(A, W, K, mb, nb, gsm,
        [&](float acc[2][8][4], int wm, int wn, int g, int tg) {
#pragma unroll
            for (int i = 0; i < 2; i++) {
                int row = mb + wm + i * 16 + g;
#pragma unroll
                for (int j = 0; j < 8; j++) {
                    int col = nb + wn + j * 8 + tg * 2;
                    *(float2*)(C + (size_t)row * N + col) =
                        make_float2(acc[i][j][0], acc[i][j][1]);
                    *(float2*)(C + (size_t)(row + 8) * N + col) =
                        make_float2(acc[i][j][2], acc[i][j][3]);
                }
            }
        });
}

// Fused QKV projection + RoPE + V-transpose epilogues (round-14 proven).
__global__ __launch_bounds__(256, 2) void gemm_qkv(const __half* __restrict__ A,
                                                   const __half* __restrict__ Wq,
                                                   const __half* __restrict__ Wkv,
                                                   __half* __restrict__ qth,
                                                   __half* __restrict__ kh,
                                                   __half* __restrict__ vth,
                                                   const int* __restrict__ pos_ids) {
    extern __shared__ char gsm[];
    float* st = (float*)gsm;   // 128 x 132 fp32 staging (reuses pipeline smem)
    const int tid = threadIdx.x;
    const int bid = blockIdx.x;

    int mb, nb;
    const __half* Wp;
    if (bid < 512) { mb = (bid >> 5) * 128; nb = (bid & 31) * 128; Wp = Wq; }
    else { int b2 = bid - 512; mb = (b2 >> 4) * 128; nb = (b2 & 15) * 128; Wp = Wkv; }

    hgemm_tile_core(A, Wp, HID, mb, nb, gsm,
        [&](float acc[2][8][4], int wm, int wn, int g, int tg) {
#pragma unroll
            for (int i = 0; i < 2; i++) {
                int r = wm + i * 16 + g;
#pragma unroll
                for (int j = 0; j < 8; j++) {
                    int c = wn + j * 8 + tg * 2;
                    *(float2*)&st[r * SST + c] =
                        make_float2(acc[i][j][0], acc[i][j][1]);
                    *(float2*)&st[(r + 8) * SST + c] =
                        make_float2(acc[i][j][2], acc[i][j][3]);
                }
            }
            __syncthreads();

            const float cexp = 0.20503692556210917f;   // ln(500000)/64
            const float sm_scale = 0.08838834764831845f;

            if (bid < 512 || nb < 1024) {
                const bool is_q = (bid < 512);
                const int head = nb >> 7;
                __half* dst = is_q ? (qth + head * HD) : (kh + head * HD);
                const int rs = is_q ? HID : KVHID;
                const float scl = is_q ? sm_scale : 1.0f;
#pragma unroll 4
                for (int j = 0; j < 32; j++) {
                    int idx = tid + 256 * j;        // 8192 = 128 rows x 64 d
                    int d = idx & 63, r = idx >> 6;
                    float x1 = st[r * SST + d];
                    float x2 = st[r * SST + d + 64];
                    float inv_freq = expf(-(float)d * cexp);
                    float fr = (float)pos_ids[mb + r] * inv_freq;
                    float cs, sn;
                    sincosf(fr, &sn, &cs);
                    size_t o = (size_t)(mb + r) * rs + d;
                    dst[o]      = __float2half_rn((x1 * cs - x2 * sn) * scl);
                    dst[o + 64] = __float2half_rn((x2 * cs + x1 * sn) * scl);
                }
            } else {
                const int head = (nb - 1024) >> 7;
                __half* dst = vth + (size_t)head * HD * SEQ;
#pragma unroll 4
                for (int j = 0; j < 64; j++) {
                    int idx = tid + 256 * j;        // 16384 = 128 d x 128 rows
                    int d = idx >> 7, r = idx & 127;
                    dst[(size_t)d * SEQ + mb + r] =
                        __float2half_rn(st[r * SST + d]);
                }
            }
        });
}

// ---------------------------------------------------------------------------
// fp16 mma flash attention v6: 64 q x 128-key tiles, ldmatrix fragments.
// ---------------------------------------------------------------------------
#define QKH 136
#define SSW 132
#define KT  128
#define ATTN_SMEM (64*QKH*2 + 2*KT*QKH*2 + KT*QKH*2 + 64*SSW*4 + 64*QKH*2 + 3*64*4)

__global__ __launch_bounds__(512) void attn_mma(const __half* __restrict__ Qt,
                                                const __half* __restrict__ Kh,
                                                const __half* __restrict__ Vt_g,
                                                __half* __restrict__ O) {
    extern __shared__ char asm_[];
    __half* Qs = (__half*)asm_;                  // 64 x 136
    __half* Ks = Qs + 64 * QKH;                  // 2 x 128 x 136
    __half* Vt = Ks + 2 * KT * QKH;              // 128(d) x 136
    float*  Ss = (float*)(Vt + KT * QKH);        // 64 x 132 fp32
    __half* Php = (__half*)(Ss + 64 * SSW);      // 64 x 136 fp16
    float*  ms = (float*)(Php + 64 * QKH);
    float*  ls = ms + 64;
    float*  fct = ls + 64;

    const uint32_t sbase = (uint32_t)__cvta_generic_to_shared(asm_);
    const uint32_t sQ  = sbase;
    const uint32_t sK  = sQ + 64 * QKH * 2;
    const uint32_t sV  = sK + 2 * KT * QKH * 2;
    const uint32_t sPh = sV + KT * QKH * 2 + 64 * SSW * 4;

    const int tid  = threadIdx.x;
    const int lane = tid & 31;
    const int wid  = tid >> 5;
    const int g    = lane >> 2;
    const int tg   = lane & 3;
    const int m0   = (wid >> 2) * 16;
    const int n0   = (wid & 3) * 32;
    const int lrow = lane & 15;
    const int lcol = (lane >> 4) * 8;

    const int qt   = blockIdx.x;
    const int head = blockIdx.y;
    const int kvh  = head >> 2;

    const __half* qp  = Qt + (size_t)qt * 64 * HID + head * HD;
    const __half* kp  = Kh + kvh * HD;
    const __half* vtp = Vt_g + (size_t)kvh * HD * SEQ;

    auto load_q = [&]() {
#pragma unroll
        for (int j = 0; j < 2; j++) {
            int idx = tid + 512 * j;
            int row = idx >> 4, ch = idx & 15;
            cp16(sQ + (uint32_t)(row * QKH * 2 + ch * 16),
                 qp + (size_t)row * HID + ch * 8);
        }
    };
    auto load_k = [&](int kt, int buf) {
        const uint32_t sdst = sK + (uint32_t)(buf * KT * QKH * 2);
#pragma unroll
        for (int j = 0; j < 4; j++) {
            int idx = tid + 512 * j;
            int row = idx >> 4, ch = idx & 15;
            cp16(sdst + (uint32_t)(row * QKH * 2 + ch * 16),
                 kp + (size_t)(kt * KT + row) * KVHID + ch * 8);
        }
    };
    auto load_vt = [&](int kt) {
#pragma unroll
        for (int j = 0; j < 4; j++) {
            int idx = tid + 512 * j;
            int d = idx >> 4, ch = idx & 15;
            cp16(sV + (uint32_t)(d * QKH * 2 + ch * 16),
                 vtp + (size_t)d * SEQ + kt * KT + ch * 8);
        }
    };

    load_q();
    cp_commit();
    load_k(0, 0);
    cp_commit();
    load_vt(0);
    cp_commit();

    if (tid < 64) { ms[tid] = -1e30f; ls[tid] = 0.f; }

    float accO[4][4];
#pragma unroll
    for (int nt = 0; nt < 4; nt++)
#pragma unroll
        for (int t = 0; t < 4; t++) accO[nt][t] = 0.f;

    cp_wait<1>();
    __syncthreads();

    // Hoist Q fragments via ldmatrix
    uint32_t qf[8][4];
#pragma unroll
    for (int k0 = 0; k0 < 8; k0++)
        ldsm_x4(qf[k0], sQ + (uint32_t)(((m0 + lrow) * QKH + k0 * 16 + lcol) * 2));

    for (int kt = 0; kt < SEQ / KT; kt++) {
        const int kb = kt & 1;
        if (kt + 1 < SEQ / KT) load_k(kt + 1, kb ^ 1);
        cp_commit();

        // --- S = Q K^T (ldmatrix B fragments) ---
        const uint32_t sKb = sK + (uint32_t)(kb * KT * QKH * 2);
        float accS[4][4];
#pragma unroll
        for (int nt = 0; nt < 4; nt++)
#pragma unroll
            for (int t = 0; t < 4; t++) accS[nt][t] = 0.f;

#pragma unroll
        for (int k0 = 0; k0 < 8; k0++) {
#pragma unroll
            for (int np = 0; np < 2; np++) {
                uint32_t t[4];
                ldsm_x4(t, sKb + (uint32_t)(((n0 + np * 16 + lrow) * QKH
                                             + k0 * 16 + lcol) * 2));
                uint32_t b0[2] = {t[0], t[2]};
                uint32_t b1[2] = {t[1], t[3]};
                mma_f16(accS[2 * np],     qf[k0], b0);
                mma_f16(accS[2 * np + 1], qf[k0], b1);
            }
        }

#pragma unroll
        for (int nt = 0; nt < 4; nt++) {
            int col = n0 + nt * 8 + tg * 2;
            *(float2*)(Ss + (m0 + g) * SSW + col) =
                make_float2(accS[nt][0], accS[nt][1]);
            *(float2*)(Ss + (m0 + g + 8) * SSW + col) =
                make_float2(accS[nt][2], accS[nt][3]);
        }
        __syncthreads();

        // --- online softmax over 128 cols; pack P to fp16 ---
        {
            int row = tid >> 3, qq = tid & 7;
            const float* srow = Ss + row * SSW + qq * 16;
            float sv[16];
#pragma unroll
            for (int j = 0; j < 16; j++) sv[j] = srow[j];
            float mx = sv[0];
#pragma unroll
            for (int j = 1; j < 16; j++) mx = fmaxf(mx, sv[j]);
            mx = fmaxf(mx, __shfl_xor_sync(0xffffffffu, mx, 1));
            mx = fmaxf(mx, __shfl_xor_sync(0xffffffffu, mx, 2));
            mx = fmaxf(mx, __shfl_xor_sync(0xffffffffu, mx, 4));
            float m_old = ms[row];
            float m_new = fmaxf(m_old, mx);
            float sum = 0.f;
#pragma unroll
            for (int j = 0; j < 16; j++) {
                sv[j] = __expf(sv[j] - m_new);
                sum += sv[j];
            }
            __half2* ph = (__half2*)(Php + row * QKH + qq * 16);
#pragma unroll
            for (int j = 0; j < 8; j++)
                ph[j] = __floats2half2_rn(sv[2 * j], sv[2 * j + 1]);
            sum += __shfl_xor_sync(0xffffffffu, sum, 1);
            sum += __shfl_xor_sync(0xffffffffu, sum, 2);
            sum += __shfl_xor_sync(0xffffffffu, sum, 4);
            if (qq == 0) {
                float f = __expf(m_old - m_new);
                fct[row] = f;
                ls[row] = ls[row] * f + sum;
                ms[row] = m_new;
            }
        }
        __syncthreads();

        cp_wait<1>();      // V(t) done (only K(t+1) may stay pending)
        __syncthreads();

        // --- rescale accumulators, O += P V (ldmatrix fragments) ---
        {
            float f0 = fct[m0 + g];
            float f1 = fct[m0 + g + 8];
#pragma unroll
            for (int nt = 0; nt < 4; nt++) {
                accO[nt][0] *= f0; accO[nt][1] *= f0;
                accO[nt][2] *= f1; accO[nt][3] *= f1;
            }
        }
#pragma unroll
        for (int k0 = 0; k0 < 8; k0++) {
            uint32_t pa[4];
            ldsm_x4(pa, sPh + (uint32_t)(((m0 + lrow) * QKH + k0 * 16 + lcol) * 2));
#pragma unroll
            for (int np = 0; np < 2; np++) {
                uint32_t t[4];
                ldsm_x4(t, sV + (uint32_t)(((n0 + np * 16 + lrow) * QKH
                                            + k0 * 16 + lcol) * 2));
                uint32_t b0[2] = {t[0], t[2]};
                uint32_t b1[2] = {t[1], t[3]};
                mma_f16(accO[2 * np],     pa, b0);
                mma_f16(accO[2 * np + 1], pa, b1);
            }
        }
        __syncthreads();   // all PV reads of Vt complete

        if (kt + 1 < SEQ / KT) load_vt(kt + 1);
        cp_commit();

        cp_wait<1>();      // K(t+1) done
        __syncthreads();
    }

    // --- finalize: divide by l, emit fp16 ---
    float inv0 = 1.0f / ls[m0 + g];
    float inv1 = 1.0f / ls[m0 + g + 8];
    __half* op = O + (size_t)qt * 64 * HID + head * HD;
#pragma unroll
    for (int nt = 0; nt < 4; nt++) {
        int col = n0 + nt * 8 + tg * 2;
        *(__half2*)(op + (size_t)(m0 + g) * HID + col) =
            __floats2half2_rn(accO[nt][0] * inv0, accO[nt][1] * inv0);
        *(__half2*)(op + (size_t)(m0 + g + 8) * HID + col) =
            __floats2half2_rn(accO[nt][2] * inv1, accO[nt][3] * inv1);
    }
}

// ---------------------------------------------------------------------------
// Launch
// ---------------------------------------------------------------------------
extern "C" void kernel_launch(void* const* d_in, const int* in_sizes, int n_in,
                              void* d_out, int out_size) {
    (void)in_sizes; (void)n_in; (void)out_size;
    const float* hs  = (const float*)d_in[0];
    const int*   pos = (const int*)d_in[1];
    const float* qw  = (const float*)d_in[2];
    const float* kw  = (const float*)d_in[3];
    const float* vw  = (const float*)d_in[4];
    const float* ow  = (const float*)d_in[5];
    float* out = (float*)d_out;

    __half *qth, *kh, *vth, *attnh, *hsh, *qwh, *kvwh, *owh;
    cudaGetSymbolAddress((void**)&qth, g_qth);
    cudaGetSymbolAddress((void**)&kh, g_kh);
    cudaGetSymbolAddress((void**)&vth, g_vth);
    cudaGetSymbolAddress((void**)&attnh, g_attnh);
    cudaGetSymbolAddress((void**)&hsh, g_hsh);
    cudaGetSymbolAddress((void**)&qwh, g_qwh);
    cudaGetSymbolAddress((void**)&kvwh, g_kvwh);
    cudaGetSymbolAddress((void**)&owh, g_owh);

    cudaFuncSetAttribute(gemm_f16,
                         cudaFuncAttributeMaxDynamicSharedMemorySize, HGEMM_SMEM);
    cudaFuncSetAttribute(gemm_qkv,
                         cudaFuncAttributeMaxDynamicSharedMemorySize, HGEMM_SMEM);
    cudaFuncSetAttribute(attn_mma,
                         cudaFuncAttributeMaxDynamicSharedMemorySize, ATTN_SMEM);

    // Fused fp16 conversion of all inputs (one launch, MLP 4)
    cvt_all<<<CVT_BLOCKS, 256>>>(hs, qw, kw, vw, ow, hsh, qwh, kvwh, owh);

    // Fused Q + KV projections with RoPE / V-transpose epilogues
    gemm_qkv<<<768, 256, HGEMM_SMEM>>>(hsh, qwh, kvwh, qth, kh, vth, pos);

    // Attention (fp16 mma + ldmatrix, 128-key tiles)
    attn_mma<<<dim3(SEQ / 64, NH), 512, ATTN_SMEM>>>(qth, kh, vth, attnh);

    // Output projection (fp16 mma + ldmatrix)
    gemm_f16<<<dim3(HID / 128, SEQ / 128), 256, HGEMM_SMEM>>>(attnh, owh, out, HID, HID);
}

// round 16
// speedup vs baseline: 1.0019x; 1.0019x over previous
#include <cuda_runtime.h>
#include <cuda_bf16.h>
#include <cuda_fp16.h>
#include <stdint.h>
#include <math.h>

// Problem constants
#define SEQ   2048
#define HID   4096
#define NH    32
#define NKV   8
#define HD    128
#define KVHID 1024      // NKV*HD
#define KVW   2048      // merged k|v row width

// Scratch (device globals; allocation-free rule)
__device__ __half g_qth[SEQ * HID];      // roped, scaled Q (fp16)
__device__ __half g_kh[SEQ * KVHID];     // roped K (fp16)
__device__ __half g_vth[NKV * HD * SEQ]; // V^T (fp16): [kvh][d][s]
__device__ __half g_attnh[SEQ * HID];    // attention output (fp16)

// fp16 copies of inputs for tensor-core GEMMs
__device__ __half g_hsh[SEQ * HID];
__device__ __half g_qwh[HID * HID];
__device__ __half g_kvwh[KVW * HID];     // rows 0-1023 = k_proj, 1024-2047 = v_proj
__device__ __half g_owh[HID * HID];

// ---------------------------------------------------------------------------
// Helpers
// ---------------------------------------------------------------------------
// mma with SCALAR b operands: lets ldmatrix outputs feed mma directly with
// no repacking MOVs (the round-15 regression source).
__device__ __forceinline__ void mma_f16(float* c, const uint32_t* a,
                                        uint32_t b0, uint32_t b1) {
    asm volatile(
        "mma.sync.aligned.m16n8k16.row.col.f32.f16.f16.f32 "
        "{%0,%1,%2,%3}, {%4,%5,%6,%7}, {%8,%9}, {%0,%1,%2,%3};"
        : "+f"(c[0]), "+f"(c[1]), "+f"(c[2]), "+f"(c[3])
        : "r"(a[0]), "r"(a[1]), "r"(a[2]), "r"(a[3]), "r"(b0), "r"(b1));
}

// ldmatrix x4: four 8x8 b16 matrices. For a 16x16 A-region (rows=m, contig k):
// r0=(m=g,k=2tg..), r1=(m=g+8,k lo), r2=(g,k hi), r3=(g+8,k hi) == A fragment.
// For a 16-row B-region (rows=n, contig k): r0=b0 of n8-tile even, r1=b0 of
// tile odd, r2=b1 even, r3=b1 odd.
__device__ __forceinline__ void ldsm_x4(uint32_t* r, uint32_t addr) {
    asm volatile(
        "ldmatrix.sync.aligned.m8n8.x4.shared.b16 {%0,%1,%2,%3}, [%4];"
        : "=r"(r[0]), "=r"(r[1]), "=r"(r[2]), "=r"(r[3])
        : "r"(addr));
}

__device__ __forceinline__ void cp16(uint32_t saddr, const void* gaddr) {
    asm volatile("cp.async.cg.shared.global [%0], [%1], 16;"
                 :: "r"(saddr), "l"(gaddr));
}
__device__ __forceinline__ void cp_commit() {
    asm volatile("cp.async.commit_group;");
}
template <int N>
__device__ __forceinline__ void cp_wait() {
    asm volatile("cp.async.wait_group %0;" :: "n"(N));
}

// ---------------------------------------------------------------------------
// Fused fp32->fp16 conversion of all 5 inputs, one launch, MLP=4.
// ---------------------------------------------------------------------------
#define CVT_S0 (SEQ * HID / 4)                         // hs    : 2M
#define CVT_S1 (CVT_S0 + HID * HID / 4)                // qw    : +4M
#define CVT_S2 (CVT_S1 + KVHID * HID / 4)              // kw    : +1M
#define CVT_S3 (CVT_S2 + KVHID * HID / 4)              // vw    : +1M
#define CVT_S4 (CVT_S3 + HID * HID / 4)                // ow    : +4M
#define CVT_BLOCKS (CVT_S4 / 1024)

__global__ __launch_bounds__(256) void cvt_all(const float* __restrict__ hs,
                                               const float* __restrict__ qw,
                                               const float* __restrict__ kw,
                                               const float* __restrict__ vw,
                                               const float* __restrict__ ow,
                                               __half* __restrict__ hsh,
                                               __half* __restrict__ qwh,
                                               __half* __restrict__ kvwh,
                                               __half* __restrict__ owh) {
    const long long base = (long long)blockIdx.x * 1024;
    const float* src;
    __half2* dst;
    long long off;
    if (base < CVT_S0)      { src = hs; dst = (__half2*)hsh;  off = base; }
    else if (base < CVT_S1) { src = qw; dst = (__half2*)qwh;  off = base - CVT_S0; }
    else if (base < CVT_S2) { src = kw; dst = (__half2*)kvwh; off = base - CVT_S1; }
    else if (base < CVT_S3) { src = vw; dst = (__half2*)(kvwh + (size_t)KVHID * HID);
                              off = base - CVT_S2; }
    else                    { src = ow; dst = (__half2*)owh;  off = base - CVT_S3; }

    float4 x[4];
#pragma unroll
    for (int j = 0; j < 4; j++)
        x[j] = ((const float4*)src)[off + threadIdx.x + j * 256];
#pragma unroll
    for (int j = 0; j < 4; j++) {
        long long f = off + threadIdx.x + j * 256;
        dst[2 * f]     = __floats2half2_rn(x[j].x, x[j].y);
        dst[2 * f + 1] = __floats2half2_rn(x[j].z, x[j].w);
    }
}

// ---------------------------------------------------------------------------
// fp16 tensor-core GEMM core: ldmatrix fragments consumed directly by mma.
// ---------------------------------------------------------------------------
#define HSTRIDE 72
#define HSTAGES 3
#define HGEMM_SMEM (HSTAGES * 2 * 128 * HSTRIDE * 2)   // 110592 B
#define SST 132   // fp32 smem staging stride (EVEN -> float2-aligned; 4 mod 32)

template <typename EPI>
__device__ __forceinline__ void hgemm_tile_core(const __half* __restrict__ A,
                                                const __half* __restrict__ W,
                                                int K, int mb, int nb,
                                                char* gsm, EPI&& epi) {
    __half* As = (__half*)gsm;                       // [3][128][72]
    __half* Bs = As + HSTAGES * 128 * HSTRIDE;

    const int tid  = threadIdx.x;
    const int lane = tid & 31;
    const int wid  = tid >> 5;
    const int g    = lane >> 2;
    const int tg   = lane & 3;
    const int wm   = (wid >> 1) * 32;
    const int wn   = (wid & 1) * 64;
    const int lrow = lane & 15;          // ldmatrix row within 16-row region
    const int lcol = (lane >> 4) * 8;    // ldmatrix k-half (halves)

    const __half* Ap = A + (size_t)mb * K;
    const __half* Wp = W + (size_t)nb * K;

    const uint32_t sA = (uint32_t)__cvta_generic_to_shared(As);
    const uint32_t sB = (uint32_t)__cvta_generic_to_shared(Bs);

    auto issue_stage = [&](int stage, int k0) {
        const uint32_t so = (uint32_t)(stage * 128 * HSTRIDE * 2);
#pragma unroll
        for (int j = 0; j < 4; j++) {
            int idx = tid + 256 * j;
            int row = idx >> 3, ch = idx & 7;
            uint32_t sofs = so + (uint32_t)(row * HSTRIDE * 2 + ch * 16);
            cp16(sA + sofs, Ap + (size_t)row * K + k0 + ch * 8);
            cp16(sB + sofs, Wp + (size_t)row * K + k0 + ch * 8);
        }
    };

    float acc[2][8][4];
#pragma unroll
    for (int i = 0; i < 2; i++)
#pragma unroll
        for (int j = 0; j < 8; j++)
#pragma unroll
            for (int t = 0; t < 4; t++) acc[i][j][t] = 0.f;

    const int NIT = K / 64;
    issue_stage(0, 0);  cp_commit();
    issue_stage(1, 64); cp_commit();
    cp_wait<1>();
    __syncthreads();

    // loop-invariant parts of ldmatrix addresses
    const uint32_t aBase0 = sA + (uint32_t)(((wm + lrow) * HSTRIDE + lcol) * 2);
    const uint32_t aBase1 = aBase0 + (uint32_t)(16 * HSTRIDE * 2);
    const uint32_t bBase  = sB + (uint32_t)(((wn + lrow) * HSTRIDE + lcol) * 2);

    for (int it = 0; it < NIT; it++) {
        const int s = it % HSTAGES;
        const uint32_t soff = (uint32_t)(s * 128 * HSTRIDE * 2);

#pragma unroll
        for (int kk = 0; kk < 4; kk++) {
            const uint32_t ko = soff + (uint32_t)(kk * 32);
            uint32_t a0[4], a1[4];
            ldsm_x4(a0, aBase0 + ko);
            ldsm_x4(a1, aBase1 + ko);
#pragma unroll
            for (int jj = 0; jj < 4; jj++) {
                uint32_t t[4];
                ldsm_x4(t, bBase + ko + (uint32_t)(jj * 16 * HSTRIDE * 2));
                mma_f16(acc[0][2 * jj],     a0, t[0], t[2]);
                mma_f16(acc[0][2 * jj + 1], a0, t[1], t[3]);
                mma_f16(acc[1][2 * jj],     a1, t[0], t[2]);
                mma_f16(acc[1][2 * jj + 1], a1, t[1], t[3]);
            }
        }

        if (it + 2 < NIT) issue_stage((it + 2) % HSTAGES, (it + 2) * 64);
        cp_commit();
        cp_wait<1>();
        __syncthreads();
    }

    epi(acc, wm, wn, g, tg);
}

// o_proj: plain fp32 store epilogue
__global__ __launch_bounds__(256, 2) void gemm_f16(const __half* __restrict__ A,
                                                   const __half* __restrict__ W,
                                                   float* __restrict__ C,
                                                   int N, int K) {
    extern __shared__ char gsm[];
    const int mb = blockIdx.y * 128, nb = blockIdx.x * 128;
    hgemm_tile_core(A, W, K, mb, nb, gsm,
        [&](float acc[2][8][4], int wm, int wn, int g, int tg) {
#pragma unroll
            for (int i = 0; i < 2; i++) {
                int row = mb + wm + i * 16 + g;
#pragma unroll
                for (int j = 0; j < 8; j++) {
                    int col = nb + wn + j * 8 + tg * 2;
                    *(float2*)(C + (size_t)row * N + col) =
                        make_float2(acc[i][j][0], acc[i][j][1]);
                    *(float2*)(C + (size_t)(row + 8) * N + col) =
                        make_float2(acc[i][j][2], acc[i][j][3]);
                }
            }
        });
}

// Fused QKV projection + RoPE + V-transpose epilogues (round-14 proven).
__global__ __launch_bounds__(256, 2) void gemm_qkv(const __half* __restrict__ A,
                                                   const __half* __restrict__ Wq,
                                                   const __half* __restrict__ Wkv,
                                                   __half* __restrict__ qth,
                                                   __half* __restrict__ kh,
                                                   __half* __restrict__ vth,
                                                   const int* __restrict__ pos_ids) {
    extern __shared__ char gsm[];
    float* st = (float*)gsm;   // 128 x 132 fp32 staging (reuses pipeline smem)
    const int tid = threadIdx.x;
    const int bid = blockIdx.x;

    int mb, nb;
    const __half* Wp;
    if (bid < 512) { mb = (bid >> 5) * 128; nb = (bid & 31) * 128; Wp = Wq; }
    else { int b2 = bid - 512; mb = (b2 >> 4) * 128; nb = (b2 & 15) * 128; Wp = Wkv; }

    hgemm_tile_core(A, Wp, HID, mb, nb, gsm,
        [&](float acc[2][8][4], int wm, int wn, int g, int tg) {
#pragma unroll
            for (int i = 0; i < 2; i++) {
                int r = wm + i * 16 + g;
#pragma unroll
                for (int j = 0; j < 8; j++) {
                    int c = wn + j * 8 + tg * 2;
                    *(float2*)&st[r * SST + c] =
                        make_float2(acc[i][j][0], acc[i][j][1]);
                    *(float2*)&st[(r + 8) * SST + c] =
                        make_float2(acc[i][j][2], acc[i][j][3]);
                }
            }
            __syncthreads();

            const float cexp = 0.20503692556210917f;   // ln(500000)/64
            const float sm_scale = 0.08838834764831845f;

            if (bid < 512 || nb < 1024) {
                const bool is_q = (bid < 512);
                const int head = nb >> 7;
                __half* dst = is_q ? (qth + head * HD) : (kh + head * HD);
                const int rs = is_q ? HID : KVHID;
                const float scl = is_q ? sm_scale : 1.0f;
#pragma unroll 4
                for (int j = 0; j < 32; j++) {
                    int idx = tid + 256 * j;        // 8192 = 128 rows x 64 d
                    int d = idx & 63, r = idx >> 6;
                    float x1 = st[r * SST + d];
                    float x2 = st[r * SST + d + 64];
                    float inv_freq = expf(-(float)d * cexp);
                    float fr = (float)pos_ids[mb + r] * inv_freq;
                    float cs, sn;
                    sincosf(fr, &sn, &cs);
                    size_t o = (size_t)(mb + r) * rs + d;
                    dst[o]      = __float2half_rn((x1 * cs - x2 * sn) * scl);
                    dst[o + 64] = __float2half_rn((x2 * cs + x1 * sn) * scl);
                }
            } else {
                const int head = (nb - 1024) >> 7;
                __half* dst = vth + (size_t)head * HD * SEQ;
#pragma unroll 4
                for (int j = 0; j < 64; j++) {
                    int idx = tid + 256 * j;        // 16384 = 128 d x 128 rows
                    int d = idx >> 7, r = idx & 127;
                    dst[(size_t)d * SEQ + mb + r] =
                        __float2half_rn(st[r * SST + d]);
                }
            }
        });
}

// ---------------------------------------------------------------------------
// fp16 mma flash attention v7: 64 q x 128-key tiles, ldmatrix direct operands.
// ---------------------------------------------------------------------------
#define QKH 136
#define SSW 132
#define KT  128
#define ATTN_SMEM (64*QKH*2 + 2*KT*QKH*2 + KT*QKH*2 + 64*SSW*4 + 64*QKH*2 + 3*64*4)

__global__ __launch_bounds__(512) void attn_mma(const __half* __restrict__ Qt,
                                                const __half* __restrict__ Kh,
                                                const __half* __restrict__ Vt_g,
                                                __half* __restrict__ O) {
    extern __shared__ char asm_[];
    __half* Qs = (__half*)asm_;                  // 64 x 136
    __half* Ks = Qs + 64 * QKH;                  // 2 x 128 x 136
    __half* Vt = Ks + 2 * KT * QKH;              // 128(d) x 136
    float*  Ss = (float*)(Vt + KT * QKH);        // 64 x 132 fp32
    __half* Php = (__half*)(Ss + 64 * SSW);      // 64 x 136 fp16
    float*  ms = (float*)(Php + 64 * QKH);
    float*  ls = ms + 64;
    float*  fct = ls + 64;

    const uint32_t sbase = (uint32_t)__cvta_generic_to_shared(asm_);
    const uint32_t sQ  = sbase;
    const uint32_t sK  = sQ + 64 * QKH * 2;
    const uint32_t sV  = sK + 2 * KT * QKH * 2;
    const uint32_t sPh = sV + KT * QKH * 2 + 64 * SSW * 4;

    const int tid  = threadIdx.x;
    const int lane = tid & 31;
    const int wid  = tid >> 5;
    const int g    = lane >> 2;
    const int tg   = lane & 3;
    const int m0   = (wid >> 2) * 16;
    const int n0   = (wid & 3) * 32;
    const int lrow = lane & 15;
    const int lcol = (lane >> 4) * 8;

    const int qt   = blockIdx.x;
    const int head = blockIdx.y;
    const int kvh  = head >> 2;

    const __half* qp  = Qt + (size_t)qt * 64 * HID + head * HD;
    const __half* kp  = Kh + kvh * HD;
    const __half* vtp = Vt_g + (size_t)kvh * HD * SEQ;

    auto load_q = [&]() {
#pragma unroll
        for (int j = 0; j < 2; j++) {
            int idx = tid + 512 * j;
            int row = idx >> 4, ch = idx & 15;
            cp16(sQ + (uint32_t)(row * QKH * 2 + ch * 16),
                 qp + (size_t)row * HID + ch * 8);
        }
    };
    auto load_k = [&](int kt, int buf) {
        const uint32_t sdst = sK + (uint32_t)(buf * KT * QKH * 2);
#pragma unroll
        for (int j = 0; j < 4; j++) {
            int idx = tid + 512 * j;
            int row = idx >> 4, ch = idx & 15;
            cp16(sdst + (uint32_t)(row * QKH * 2 + ch * 16),
                 kp + (size_t)(kt * KT + row) * KVHID + ch * 8);
        }
    };
    auto load_vt = [&](int kt) {
#pragma unroll
        for (int j = 0; j < 4; j++) {
            int idx = tid + 512 * j;
            int d = idx >> 4, ch = idx & 15;
            cp16(sV + (uint32_t)(d * QKH * 2 + ch * 16),
                 vtp + (size_t)d * SEQ + kt * KT + ch * 8);
        }
    };

    load_q();
    cp_commit();
    load_k(0, 0);
    cp_commit();
    load_vt(0);
    cp_commit();

    if (tid < 64) { ms[tid] = -1e30f; ls[tid] = 0.f; }

    float accO[4][4];
#pragma unroll
    for (int nt = 0; nt < 4; nt++)
#pragma unroll
        for (int t = 0; t < 4; t++) accO[nt][t] = 0.f;

    cp_wait<1>();
    __syncthreads();

    // Hoist Q fragments via ldmatrix
    uint32_t qf[8][4];
#pragma unroll
    for (int k0 = 0; k0 < 8; k0++)
        ldsm_x4(qf[k0], sQ + (uint32_t)(((m0 + lrow) * QKH + k0 * 16 + lcol) * 2));

    // loop-invariant ldmatrix bases
    const uint32_t kBase = sK + (uint32_t)(((n0 + lrow) * QKH + lcol) * 2);
    const uint32_t vBase = sV + (uint32_t)(((n0 + lrow) * QKH + lcol) * 2);
    const uint32_t pBase = sPh + (uint32_t)(((m0 + lrow) * QKH + lcol) * 2);

    for (int kt = 0; kt < SEQ / KT; kt++) {
        const int kb = kt & 1;
        if (kt + 1 < SEQ / KT) load_k(kt + 1, kb ^ 1);
        cp_commit();

        // --- S = Q K^T (ldmatrix B fragments, direct operands) ---
        const uint32_t kOff = (uint32_t)(kb * KT * QKH * 2);
        float accS[4][4];
#pragma unroll
        for (int nt = 0; nt < 4; nt++)
#pragma unroll
            for (int t = 0; t < 4; t++) accS[nt][t] = 0.f;

#pragma unroll
        for (int k0 = 0; k0 < 8; k0++) {
#pragma unroll
            for (int np = 0; np < 2; np++) {
                uint32_t t[4];
                ldsm_x4(t, kBase + kOff + (uint32_t)((np * 16 * QKH + k0 * 16) * 2));
                mma_f16(accS[2 * np],     qf[k0], t[0], t[2]);
                mma_f16(accS[2 * np + 1], qf[k0], t[1], t[3]);
            }
        }

#pragma unroll
        for (int nt = 0; nt < 4; nt++) {
            int col = n0 + nt * 8 + tg * 2;
            *(float2*)(Ss + (m0 + g) * SSW + col) =
                make_float2(accS[nt][0], accS[nt][1]);
            *(float2*)(Ss + (m0 + g + 8) * SSW + col) =
                make_float2(accS[nt][2], accS[nt][3]);
        }
        __syncthreads();

        // --- online softmax over 128 cols; pack P to fp16 ---
        {
            int row = tid >> 3, qq = tid & 7;
            const float* srow = Ss + row * SSW + qq * 16;
            float sv[16];
#pragma unroll
            for (int j = 0; j < 16; j++) sv[j] = srow[j];
            float mx = sv[0];
#pragma unroll
            for (int j = 1; j < 16; j++) mx = fmaxf(mx, sv[j]);
            mx = fmaxf(mx, __shfl_xor_sync(0xffffffffu, mx, 1));
            mx = fmaxf(mx, __shfl_xor_sync(0xffffffffu, mx, 2));
            mx = fmaxf(mx, __shfl_xor_sync(0xffffffffu, mx, 4));
            float m_old = ms[row];
            float m_new = fmaxf(m_old, mx);
            float sum = 0.f;
#pragma unroll
            for (int j = 0; j < 16; j++) {
                sv[j] = __expf(sv[j] - m_new);
                sum += sv[j];
            }
            __half2* ph = (__half2*)(Php + row * QKH + qq * 16);
#pragma unroll
            for (int j = 0; j < 8; j++)
                ph[j] = __floats2half2_rn(sv[2 * j], sv[2 * j + 1]);
            sum += __shfl_xor_sync(0xffffffffu, sum, 1);
            sum += __shfl_xor_sync(0xffffffffu, sum, 2);
            sum += __shfl_xor_sync(0xffffffffu, sum, 4);
            if (qq == 0) {
                float f = __expf(m_old - m_new);
                fct[row] = f;
                ls[row] = ls[row] * f + sum;
                ms[row] = m_new;
            }
        }
        __syncthreads();

        cp_wait<1>();      // V(t) done (only K(t+1) may stay pending)
        __syncthreads();

        // --- rescale accumulators, O += P V (ldmatrix direct operands) ---
        {
            float f0 = fct[m0 + g];
            float f1 = fct[m0 + g + 8];
#pragma unroll
            for (int nt = 0; nt < 4; nt++) {
                accO[nt][0] *= f0; accO[nt][1] *= f0;
                accO[nt][2] *= f1; accO[nt][3] *= f1;
            }
        }
#pragma unroll
        for (int k0 = 0; k0 < 8; k0++) {
            uint32_t pa[4];
            ldsm_x4(pa, pBase + (uint32_t)(k0 * 32));
#pragma unroll
            for (int np = 0; np < 2; np++) {
                uint32_t t[4];
                ldsm_x4(t, vBase + (uint32_t)((np * 16 * QKH + k0 * 16) * 2));
                mma_f16(accO[2 * np],     pa, t[0], t[2]);
                mma_f16(accO[2 * np + 1], pa, t[1], t[3]);
            }
        }
        __syncthreads();   // all PV reads of Vt complete

        if (kt + 1 < SEQ / KT) load_vt(kt + 1);
        cp_commit();

        cp_wait<1>();      // K(t+1) done
        __syncthreads();
    }

    // --- finalize: divide by l, emit fp16 ---
    float inv0 = 1.0f / ls[m0 + g];
    float inv1 = 1.0f / ls[m0 + g + 8];
    __half* op = O + (size_t)qt * 64 * HID + head * HD;
#pragma unroll
    for (int nt = 0; nt < 4; nt++) {
        int col = n0 + nt * 8 + tg * 2;
        *(__half2*)(op + (size_t)(m0 + g) * HID + col) =
            __floats2half2_rn(accO[nt][0] * inv0, accO[nt][1] * inv0);
        *(__half2*)(op + (size_t)(m0 + g + 8) * HID + col) =
            __floats2half2_rn(accO[nt][2] * inv1, accO[nt][3] * inv1);
    }
}

// ---------------------------------------------------------------------------
// Launch
// ---------------------------------------------------------------------------
extern "C" void kernel_launch(void* const* d_in, const int* in_sizes, int n_in,
                              void* d_out, int out_size) {
    (void)in_sizes; (void)n_in; (void)out_size;
    const float* hs  = (const float*)d_in[0];
    const int*   pos = (const int*)d_in[1];
    const float* qw  = (const float*)d_in[2];
    const float* kw  = (const float*)d_in[3];
    const float* vw  = (const float*)d_in[4];
    const float* ow  = (const float*)d_in[5];
    float* out = (float*)d_out;

    __half *qth, *kh, *vth, *attnh, *hsh, *qwh, *kvwh, *owh;
    cudaGetSymbolAddress((void**)&qth, g_qth);
    cudaGetSymbolAddress((void**)&kh, g_kh);
    cudaGetSymbolAddress((void**)&vth, g_vth);
    cudaGetSymbolAddress((void**)&attnh, g_attnh);
    cudaGetSymbolAddress((void**)&hsh, g_hsh);
    cudaGetSymbolAddress((void**)&qwh, g_qwh);
    cudaGetSymbolAddress((void**)&kvwh, g_kvwh);
    cudaGetSymbolAddress((void**)&owh, g_owh);

    cudaFuncSetAttribute(gemm_f16,
                         cudaFuncAttributeMaxDynamicSharedMemorySize, HGEMM_SMEM);
    cudaFuncSetAttribute(gemm_qkv,
                         cudaFuncAttributeMaxDynamicSharedMemorySize, HGEMM_SMEM);
    cudaFuncSetAttribute(attn_mma,
                         cudaFuncAttributeMaxDynamicSharedMemorySize, ATTN_SMEM);

    // Fused fp16 conversion of all inputs (one launch, MLP 4)
    cvt_all<<<CVT_BLOCKS, 256>>>(hs, qw, kw, vw, ow, hsh, qwh, kvwh, owh);

    // Fused Q + KV projections with RoPE / V-transpose epilogues
    gemm_qkv<<<768, 256, HGEMM_SMEM>>>(hsh, qwh, kvwh, qth, kh, vth, pos);

    // Attention (fp16 mma + ldmatrix, 128-key tiles)
    attn_mma<<<dim3(SEQ / 64, NH), 512, ATTN_SMEM>>>(qth, kh, vth, attnh);

    // Output projection (fp16 mma + ldmatrix)
    gemm_f16<<<dim3(HID / 128, SEQ / 128), 256, HGEMM_SMEM>>>(attnh, owh, out, HID, HID);
}

// round 17
// speedup vs baseline: 1.0047x; 1.0028x over previous
#include <cuda_runtime.h>
#include <cuda_bf16.h>
#include <cuda_fp16.h>
#include <stdint.h>
#include <math.h>

// Problem constants
#define SEQ   2048
#define HID   4096
#define NH    32
#define NKV   8
#define HD    128
#define KVHID 1024      // NKV*HD
#define KVW   2048      // merged k|v row width

// Scratch (device globals; allocation-free rule)
__device__ __half g_qth[SEQ * HID];      // roped, scaled Q (fp16)
__device__ __half g_kh[SEQ * KVHID];     // roped K (fp16)
__device__ __half g_vth[NKV * HD * SEQ]; // V^T (fp16): [kvh][d][s]
__device__ __half g_attnh[SEQ * HID];    // attention output (fp16)

// fp16 copies of inputs for tensor-core GEMMs
__device__ __half g_hsh[SEQ * HID];
__device__ __half g_qwh[HID * HID];
__device__ __half g_kvwh[KVW * HID];     // rows 0-1023 = k_proj, 1024-2047 = v_proj
__device__ __half g_owh[HID * HID];

// ---------------------------------------------------------------------------
// Helpers
// ---------------------------------------------------------------------------
__device__ __forceinline__ void mma_f16(float* c, const uint32_t* a,
                                        const uint32_t* b) {
    asm volatile(
        "mma.sync.aligned.m16n8k16.row.col.f32.f16.f16.f32 "
        "{%0,%1,%2,%3}, {%4,%5,%6,%7}, {%8,%9}, {%0,%1,%2,%3};"
        : "+f"(c[0]), "+f"(c[1]), "+f"(c[2]), "+f"(c[3])
        : "r"(a[0]), "r"(a[1]), "r"(a[2]), "r"(a[3]), "r"(b[0]), "r"(b[1]));
}

__device__ __forceinline__ void cp16(uint32_t saddr, const void* gaddr) {
    asm volatile("cp.async.cg.shared.global [%0], [%1], 16;"
                 :: "r"(saddr), "l"(gaddr));
}
__device__ __forceinline__ void cp_commit() {
    asm volatile("cp.async.commit_group;");
}
template <int N>
__device__ __forceinline__ void cp_wait() {
    asm volatile("cp.async.wait_group %0;" :: "n"(N));
}

// ---------------------------------------------------------------------------
// Fused fp32->fp16 conversion of all 5 inputs, one launch, MLP=4.
// ---------------------------------------------------------------------------
#define CVT_S0 (SEQ * HID / 4)                         // hs    : 2M
#define CVT_S1 (CVT_S0 + HID * HID / 4)                // qw    : +4M
#define CVT_S2 (CVT_S1 + KVHID * HID / 4)              // kw    : +1M
#define CVT_S3 (CVT_S2 + KVHID * HID / 4)              // vw    : +1M
#define CVT_S4 (CVT_S3 + HID * HID / 4)                // ow    : +4M
#define CVT_BLOCKS (CVT_S4 / 1024)

__global__ __launch_bounds__(256) void cvt_all(const float* __restrict__ hs,
                                               const float* __restrict__ qw,
                                               const float* __restrict__ kw,
                                               const float* __restrict__ vw,
                                               const float* __restrict__ ow,
                                               __half* __restrict__ hsh,
                                               __half* __restrict__ qwh,
                                               __half* __restrict__ kvwh,
                                               __half* __restrict__ owh) {
    const long long base = (long long)blockIdx.x * 1024;
    const float* src;
    __half2* dst;
    long long off;
    if (base < CVT_S0)      { src = hs; dst = (__half2*)hsh;  off = base; }
    else if (base < CVT_S1) { src = qw; dst = (__half2*)qwh;  off = base - CVT_S0; }
    else if (base < CVT_S2) { src = kw; dst = (__half2*)kvwh; off = base - CVT_S1; }
    else if (base < CVT_S3) { src = vw; dst = (__half2*)(kvwh + (size_t)KVHID * HID);
                              off = base - CVT_S2; }
    else                    { src = ow; dst = (__half2*)owh;  off = base - CVT_S3; }

    float4 x[4];
#pragma unroll
    for (int j = 0; j < 4; j++)
        x[j] = ((const float4*)src)[off + threadIdx.x + j * 256];
#pragma unroll
    for (int j = 0; j < 4; j++) {
        long long f = off + threadIdx.x + j * 256;
        dst[2 * f]     = __floats2half2_rn(x[j].x, x[j].y);
        dst[2 * f + 1] = __floats2half2_rn(x[j].z, x[j].w);
    }
}

// ---------------------------------------------------------------------------
// fp16 tensor-core GEMM core v2: CTA tile 256x128, 8 warps 4(m)x2(n),
// warp tile 64x64 (32 independent mmas per kk; LDS/mma = 1.0). occ 1.
// Scalar LDS fragment loads (proven round-14 form). 3-stage cp.async ring.
// ---------------------------------------------------------------------------
#define HSTRIDE 72
#define HSTAGES 3
#define HGEMM_SMEM (HSTAGES * (256 + 128) * HSTRIDE * 2)   // 165888 B
#define SST 132   // fp32 smem staging stride (EVEN -> float2-aligned; 4 mod 32)

template <typename EPI>
__device__ __forceinline__ void hgemm_tile_core(const __half* __restrict__ A,
                                                const __half* __restrict__ W,
                                                int K, int mb, int nb,
                                                char* gsm, EPI&& epi) {
    __half* As = (__half*)gsm;                       // [3][256][72]
    __half* Bs = As + HSTAGES * 256 * HSTRIDE;       // [3][128][72]

    const int tid  = threadIdx.x;
    const int lane = tid & 31;
    const int wid  = tid >> 5;
    const int g    = lane >> 2;
    const int tg   = lane & 3;
    const int wm   = (wid >> 1) * 64;   // 0,64,128,192
    const int wn   = (wid & 1) * 64;    // 0,64

    const __half* Ap = A + (size_t)mb * K;
    const __half* Wp = W + (size_t)nb * K;

    const uint32_t sA = (uint32_t)__cvta_generic_to_shared(As);
    const uint32_t sB = (uint32_t)__cvta_generic_to_shared(Bs);

    auto issue_stage = [&](int stage, int k0) {
        const uint32_t soA = (uint32_t)(stage * 256 * HSTRIDE * 2);
        const uint32_t soB = (uint32_t)(stage * 128 * HSTRIDE * 2);
#pragma unroll
        for (int j = 0; j < 8; j++) {            // A: 2048 16B-chunks
            int idx = tid + 256 * j;
            int row = idx >> 3, ch = idx & 7;
            cp16(sA + soA + (uint32_t)(row * HSTRIDE * 2 + ch * 16),
                 Ap + (size_t)row * K + k0 + ch * 8);
        }
#pragma unroll
        for (int j = 0; j < 4; j++) {            // B: 1024 16B-chunks
            int idx = tid + 256 * j;
            int row = idx >> 3, ch = idx & 7;
            cp16(sB + soB + (uint32_t)(row * HSTRIDE * 2 + ch * 16),
                 Wp + (size_t)row * K + k0 + ch * 8);
        }
    };

    float acc[4][8][4];
#pragma unroll
    for (int i = 0; i < 4; i++)
#pragma unroll
        for (int j = 0; j < 8; j++)
#pragma unroll
            for (int t = 0; t < 4; t++) acc[i][j][t] = 0.f;

    const int NIT = K / 64;
    issue_stage(0, 0);  cp_commit();
    issue_stage(1, 64); cp_commit();
    cp_wait<1>();
    __syncthreads();

    for (int it = 0; it < NIT; it++) {
        const int s = it % HSTAGES;
        const __half* as = As + s * 256 * HSTRIDE;
        const __half* bs = Bs + s * 128 * HSTRIDE;

#pragma unroll
        for (int kk = 0; kk < 4; kk++) {
            uint32_t af[4][4], bf[8][2];
#pragma unroll
            for (int i = 0; i < 4; i++) {
                const __half* ar = as + (wm + i * 16 + g) * HSTRIDE + kk * 16 + tg * 2;
                af[i][0] = *(const uint32_t*)ar;
                af[i][1] = *(const uint32_t*)(ar + 8 * HSTRIDE);
                af[i][2] = *(const uint32_t*)(ar + 8);
                af[i][3] = *(const uint32_t*)(ar + 8 * HSTRIDE + 8);
            }
#pragma unroll
            for (int j = 0; j < 8; j++) {
                const __half* br = bs + (wn + j * 8 + g) * HSTRIDE + kk * 16 + tg * 2;
                bf[j][0] = *(const uint32_t*)br;
                bf[j][1] = *(const uint32_t*)(br + 8);
            }
#pragma unroll
            for (int i = 0; i < 4; i++)
#pragma unroll
                for (int j = 0; j < 8; j++)
                    mma_f16(acc[i][j], af[i], bf[j]);
        }

        if (it + 2 < NIT) issue_stage((it + 2) % HSTAGES, (it + 2) * 64);
        cp_commit();
        cp_wait<1>();
        __syncthreads();
    }

    epi(acc, wm, wn, g, tg);
}

// o_proj: plain fp32 store epilogue
__global__ __launch_bounds__(256, 1) void gemm_f16(const __half* __restrict__ A,
                                                   const __half* __restrict__ W,
                                                   float* __restrict__ C,
                                                   int N, int K) {
    extern __shared__ char gsm[];
    const int mb = blockIdx.y * 256, nb = blockIdx.x * 128;
    hgemm_tile_core(A, W, K, mb, nb, gsm,
        [&](float acc[4][8][4], int wm, int wn, int g, int tg) {
#pragma unroll
            for (int i = 0; i < 4; i++) {
                int row = mb + wm + i * 16 + g;
#pragma unroll
                for (int j = 0; j < 8; j++) {
                    int col = nb + wn + j * 8 + tg * 2;
                    *(float2*)(C + (size_t)row * N + col) =
                        make_float2(acc[i][j][0], acc[i][j][1]);
                    *(float2*)(C + (size_t)(row + 8) * N + col) =
                        make_float2(acc[i][j][2], acc[i][j][3]);
                }
            }
        });
}

// Fused QKV projection + RoPE + V-transpose epilogues (256-row tiles).
// q part: 256 CTAs (8 m x 32 heads); kv part: 128 CTAs (8 m x 16 tiles).
__global__ __launch_bounds__(256, 1) void gemm_qkv(const __half* __restrict__ A,
                                                   const __half* __restrict__ Wq,
                                                   const __half* __restrict__ Wkv,
                                                   __half* __restrict__ qth,
                                                   __half* __restrict__ kh,
                                                   __half* __restrict__ vth,
                                                   const int* __restrict__ pos_ids) {
    extern __shared__ char gsm[];
    float* st = (float*)gsm;   // 256 x 132 fp32 staging (reuses pipeline smem)
    const int tid = threadIdx.x;
    const int bid = blockIdx.x;

    int mb, nb;
    const __half* Wp;
    if (bid < 256) { mb = (bid >> 5) * 256; nb = (bid & 31) * 128; Wp = Wq; }
    else { int b2 = bid - 256; mb = (b2 >> 4) * 256; nb = (b2 & 15) * 128; Wp = Wkv; }

    hgemm_tile_core(A, Wp, HID, mb, nb, gsm,
        [&](float acc[4][8][4], int wm, int wn, int g, int tg) {
            // stage accumulators to smem (even stride -> aligned float2)
#pragma unroll
            for (int i = 0; i < 4; i++) {
                int r = wm + i * 16 + g;
#pragma unroll
                for (int j = 0; j < 8; j++) {
                    int c = wn + j * 8 + tg * 2;
                    *(float2*)&st[r * SST + c] =
                        make_float2(acc[i][j][0], acc[i][j][1]);
                    *(float2*)&st[(r + 8) * SST + c] =
                        make_float2(acc[i][j][2], acc[i][j][3]);
                }
            }
            __syncthreads();

            const float cexp = 0.20503692556210917f;   // ln(500000)/64
            const float sm_scale = 0.08838834764831845f;

            if (bid < 256 || nb < 1024) {
                // q or k head: rope (+scale for q)
                const bool is_q = (bid < 256);
                const int head = nb >> 7;
                __half* dst = is_q ? (qth + head * HD) : (kh + head * HD);
                const int rs = is_q ? HID : KVHID;
                const float scl = is_q ? sm_scale : 1.0f;
#pragma unroll 4
                for (int j = 0; j < 64; j++) {
                    int idx = tid + 256 * j;        // 16384 = 256 rows x 64 d
                    int d = idx & 63, r = idx >> 6;
                    float x1 = st[r * SST + d];
                    float x2 = st[r * SST + d + 64];
                    float inv_freq = expf(-(float)d * cexp);
                    float fr = (float)pos_ids[mb + r] * inv_freq;
                    float cs, sn;
                    sincosf(fr, &sn, &cs);
                    size_t o = (size_t)(mb + r) * rs + d;
                    dst[o]      = __float2half_rn((x1 * cs - x2 * sn) * scl);
                    dst[o + 64] = __float2half_rn((x2 * cs + x1 * sn) * scl);
                }
            } else {
                // v head: transpose to [kvh][d][s]
                const int head = (nb - 1024) >> 7;
                __half* dst = vth + (size_t)head * HD * SEQ;
#pragma unroll 4
                for (int j = 0; j < 128; j++) {
                    int idx = tid + 256 * j;        // 32768 = 128 d x 256 rows
                    int d = idx >> 8, r = idx & 255;
                    dst[(size_t)d * SEQ + mb + r] =
                        __float2half_rn(st[r * SST + d]);
                }
            }
        });
}

// ---------------------------------------------------------------------------
// fp16 mma flash attention (round-14 proven, scalar LDS): 64q x 128-key tiles.
// ---------------------------------------------------------------------------
#define QKH 136
#define SSW 132
#define KT  128
#define ATTN_SMEM (64*QKH*2 + 2*KT*QKH*2 + KT*QKH*2 + 64*SSW*4 + 64*QKH*2 + 3*64*4)

__global__ __launch_bounds__(512) void attn_mma(const __half* __restrict__ Qt,
                                                const __half* __restrict__ Kh,
                                                const __half* __restrict__ Vt_g,
                                                __half* __restrict__ O) {
    extern __shared__ char asm_[];
    __half* Qs = (__half*)asm_;                  // 64 x 136
    __half* Ks = Qs + 64 * QKH;                  // 2 x 128 x 136
    __half* Vt = Ks + 2 * KT * QKH;              // 128(d) x 136
    float*  Ss = (float*)(Vt + KT * QKH);        // 64 x 132 fp32
    __half* Php = (__half*)(Ss + 64 * SSW);      // 64 x 136 fp16
    float*  ms = (float*)(Php + 64 * QKH);
    float*  ls = ms + 64;
    float*  fct = ls + 64;

    const uint32_t sbase = (uint32_t)__cvta_generic_to_shared(asm_);
    const uint32_t sQ = sbase;
    const uint32_t sK = sQ + 64 * QKH * 2;
    const uint32_t sV = sK + 2 * KT * QKH * 2;

    const int tid  = threadIdx.x;
    const int lane = tid & 31;
    const int wid  = tid >> 5;
    const int g    = lane >> 2;
    const int tg   = lane & 3;
    const int m0   = (wid >> 2) * 16;
    const int n0   = (wid & 3) * 32;

    const int qt   = blockIdx.x;
    const int head = blockIdx.y;
    const int kvh  = head >> 2;

    const __half* qp  = Qt + (size_t)qt * 64 * HID + head * HD;
    const __half* kp  = Kh + kvh * HD;
    const __half* vtp = Vt_g + (size_t)kvh * HD * SEQ;

    auto load_q = [&]() {
#pragma unroll
        for (int j = 0; j < 2; j++) {
            int idx = tid + 512 * j;
            int row = idx >> 4, ch = idx & 15;
            cp16(sQ + (uint32_t)(row * QKH * 2 + ch * 16),
                 qp + (size_t)row * HID + ch * 8);
        }
    };
    auto load_k = [&](int kt, int buf) {
        const uint32_t sdst = sK + (uint32_t)(buf * KT * QKH * 2);
#pragma unroll
        for (int j = 0; j < 4; j++) {
            int idx = tid + 512 * j;
            int row = idx >> 4, ch = idx & 15;
            cp16(sdst + (uint32_t)(row * QKH * 2 + ch * 16),
                 kp + (size_t)(kt * KT + row) * KVHID + ch * 8);
        }
    };
    auto load_vt = [&](int kt) {
#pragma unroll
        for (int j = 0; j < 4; j++) {
            int idx = tid + 512 * j;
            int d = idx >> 4, ch = idx & 15;
            cp16(sV + (uint32_t)(d * QKH * 2 + ch * 16),
                 vtp + (size_t)d * SEQ + kt * KT + ch * 8);
        }
    };

    load_q();
    cp_commit();
    load_k(0, 0);
    cp_commit();
    load_vt(0);
    cp_commit();

    if (tid < 64) { ms[tid] = -1e30f; ls[tid] = 0.f; }

    float accO[4][4];
#pragma unroll
    for (int nt = 0; nt < 4; nt++)
#pragma unroll
        for (int t = 0; t < 4; t++) accO[nt][t] = 0.f;

    cp_wait<1>();
    __syncthreads();

    // Hoist Q fragments (scalar LDS)
    uint32_t qf[8][4];
#pragma unroll
    for (int k0 = 0; k0 < 8; k0++) {
        const __half* ar = Qs + (m0 + g) * QKH + k0 * 16 + tg * 2;
        qf[k0][0] = *(const uint32_t*)ar;
        qf[k0][1] = *(const uint32_t*)(ar + 8 * QKH);
        qf[k0][2] = *(const uint32_t*)(ar + 8);
        qf[k0][3] = *(const uint32_t*)(ar + 8 * QKH + 8);
    }

    for (int kt = 0; kt < SEQ / KT; kt++) {
        const int kb = kt & 1;
        if (kt + 1 < SEQ / KT) load_k(kt + 1, kb ^ 1);
        cp_commit();

        // --- S = Q K^T ---
        const __half* ksb = Ks + kb * KT * QKH;
        float accS[4][4];
#pragma unroll
        for (int nt = 0; nt < 4; nt++)
#pragma unroll
            for (int t = 0; t < 4; t++) accS[nt][t] = 0.f;

#pragma unroll
        for (int k0 = 0; k0 < 8; k0++) {
#pragma unroll
            for (int nt = 0; nt < 4; nt++) {
                uint32_t bb[2];
                const __half* br = ksb + (n0 + nt * 8 + g) * QKH + k0 * 16 + tg * 2;
                bb[0] = *(const uint32_t*)br;
                bb[1] = *(const uint32_t*)(br + 8);
                mma_f16(accS[nt], qf[k0], bb);
            }
        }

#pragma unroll
        for (int nt = 0; nt < 4; nt++) {
            int col = n0 + nt * 8 + tg * 2;
            *(float2*)(Ss + (m0 + g) * SSW + col) =
                make_float2(accS[nt][0], accS[nt][1]);
            *(float2*)(Ss + (m0 + g + 8) * SSW + col) =
                make_float2(accS[nt][2], accS[nt][3]);
        }
        __syncthreads();

        // --- online softmax over 128 cols; pack P to fp16 ---
        {
            int row = tid >> 3, qq = tid & 7;
            const float* srow = Ss + row * SSW + qq * 16;
            float sv[16];
#pragma unroll
            for (int j = 0; j < 16; j++) sv[j] = srow[j];
            float mx = sv[0];
#pragma unroll
            for (int j = 1; j < 16; j++) mx = fmaxf(mx, sv[j]);
            mx = fmaxf(mx, __shfl_xor_sync(0xffffffffu, mx, 1));
            mx = fmaxf(mx, __shfl_xor_sync(0xffffffffu, mx, 2));
            mx = fmaxf(mx, __shfl_xor_sync(0xffffffffu, mx, 4));
            float m_old = ms[row];
            float m_new = fmaxf(m_old, mx);
            float sum = 0.f;
#pragma unroll
            for (int j = 0; j < 16; j++) {
                sv[j] = __expf(sv[j] - m_new);
                sum += sv[j];
            }
            __half2* ph = (__half2*)(Php + row * QKH + qq * 16);
#pragma unroll
            for (int j = 0; j < 8; j++)
                ph[j] = __floats2half2_rn(sv[2 * j], sv[2 * j + 1]);
            sum += __shfl_xor_sync(0xffffffffu, sum, 1);
            sum += __shfl_xor_sync(0xffffffffu, sum, 2);
            sum += __shfl_xor_sync(0xffffffffu, sum, 4);
            if (qq == 0) {
                float f = __expf(m_old - m_new);
                fct[row] = f;
                ls[row] = ls[row] * f + sum;
                ms[row] = m_new;
            }
        }
        __syncthreads();

        cp_wait<1>();      // V(t) done (only K(t+1) may stay pending)
        __syncthreads();

        // --- rescale accumulators, O += P V ---
        {
            float f0 = fct[m0 + g];
            float f1 = fct[m0 + g + 8];
#pragma unroll
            for (int nt = 0; nt < 4; nt++) {
                accO[nt][0] *= f0; accO[nt][1] *= f0;
                accO[nt][2] *= f1; accO[nt][3] *= f1;
            }
        }
#pragma unroll
        for (int k0 = 0; k0 < 8; k0++) {
            uint32_t pa[4];
            const __half* pr = Php + (m0 + g) * QKH + k0 * 16 + tg * 2;
            pa[0] = *(const uint32_t*)pr;
            pa[1] = *(const uint32_t*)(pr + 8 * QKH);
            pa[2] = *(const uint32_t*)(pr + 8);
            pa[3] = *(const uint32_t*)(pr + 8 * QKH + 8);
#pragma unroll
            for (int nt = 0; nt < 4; nt++) {
                uint32_t vb[2];
                const __half* vr = Vt + (n0 + nt * 8 + g) * QKH + k0 * 16 + tg * 2;
                vb[0] = *(const uint32_t*)vr;
                vb[1] = *(const uint32_t*)(vr + 8);
                mma_f16(accO[nt], pa, vb);
            }
        }
        __syncthreads();   // all PV reads of Vt complete

        if (kt + 1 < SEQ / KT) load_vt(kt + 1);
        cp_commit();

        cp_wait<1>();      // K(t+1) done
        __syncthreads();
    }

    // --- finalize: divide by l, emit fp16 ---
    float inv0 = 1.0f / ls[m0 + g];
    float inv1 = 1.0f / ls[m0 + g + 8];
    __half* op = O + (size_t)qt * 64 * HID + head * HD;
#pragma unroll
    for (int nt = 0; nt < 4; nt++) {
        int col = n0 + nt * 8 + tg * 2;
        *(__half2*)(op + (size_t)(m0 + g) * HID + col) =
            __floats2half2_rn(accO[nt][0] * inv0, accO[nt][1] * inv0);
        *(__half2*)(op + (size_t)(m0 + g + 8) * HID + col) =
            __floats2half2_rn(accO[nt][2] * inv1, accO[nt][3] * inv1);
    }
}

// ---------------------------------------------------------------------------
// Launch
// ---------------------------------------------------------------------------
extern "C" void kernel_launch(void* const* d_in, const int* in_sizes, int n_in,
                              void* d_out, int out_size) {
    (void)in_sizes; (void)n_in; (void)out_size;
    const float* hs  = (const float*)d_in[0];
    const int*   pos = (const int*)d_in[1];
    const float* qw  = (const float*)d_in[2];
    const float* kw  = (const float*)d_in[3];
    const float* vw  = (const float*)d_in[4];
    const float* ow  = (const float*)d_in[5];
    float* out = (float*)d_out;

    __half *qth, *kh, *vth, *attnh, *hsh, *qwh, *kvwh, *owh;
    cudaGetSymbolAddress((void**)&qth, g_qth);
    cudaGetSymbolAddress((void**)&kh, g_kh);
    cudaGetSymbolAddress((void**)&vth, g_vth);
    cudaGetSymbolAddress((void**)&attnh, g_attnh);
    cudaGetSymbolAddress((void**)&hsh, g_hsh);
    cudaGetSymbolAddress((void**)&qwh, g_qwh);
    cudaGetSymbolAddress((void**)&kvwh, g_kvwh);
    cudaGetSymbolAddress((void**)&owh, g_owh);

    cudaFuncSetAttribute(gemm_f16,
                         cudaFuncAttributeMaxDynamicSharedMemorySize, HGEMM_SMEM);
    cudaFuncSetAttribute(gemm_qkv,
                         cudaFuncAttributeMaxDynamicSharedMemorySize, HGEMM_SMEM);
    cudaFuncSetAttribute(attn_mma,
                         cudaFuncAttributeMaxDynamicSharedMemorySize, ATTN_SMEM);

    // Fused fp16 conversion of all inputs (one launch, MLP 4)
    cvt_all<<<CVT_BLOCKS, 256>>>(hs, qw, kw, vw, ow, hsh, qwh, kvwh, owh);

    // Fused Q + KV projections with RoPE / V-transpose epilogues (384 CTAs)
    gemm_qkv<<<384, 256, HGEMM_SMEM>>>(hsh, qwh, kvwh, qth, kh, vth, pos);

    // Attention (fp16 mma, 128-key tiles)
    attn_mma<<<dim3(SEQ / 64, NH), 512, ATTN_SMEM>>>(qth, kh, vth, attnh);

    // Output projection (256x128 tiles, 256 CTAs)
    gemm_f16<<<dim3(HID / 128, SEQ / 256), 256, HGEMM_SMEM>>>(attnh, owh, out, HID, HID);
}